// round 2
// baseline (speedup 1.0000x reference)
#include <cuda_runtime.h>
#include <mma.h>
#include <cstdint>

using namespace nvcuda;

// Problem constants
#define BB 8
#define SS 2048
#define NN 8
#define DD 768
#define ROWS (BB*SS)          // 16384

// Scratch (device globals: allocation-free per harness rules)
__device__ float g_U[ROWS*DD];     // query @ (Wq^T Wk) + bq@Wk
__device__ float g_ctx[ROWS*DD];   // attention context
__device__ float g_Wp[DD*DD];      // Wq^T @ Wk
__device__ float g_bp[DD];         // bq @ Wk

// ---------------------------------------------------------------------------
// prep: b'[n] = sum_i bq[i] * Wk[i, n]
// ---------------------------------------------------------------------------
__global__ void prep_bp_kernel(const float* __restrict__ bq,
                               const float* __restrict__ Wk,
                               float* __restrict__ bp) {
    int n = blockIdx.x * blockDim.x + threadIdx.x;
    if (n >= DD) return;
    float acc = 0.f;
    #pragma unroll 4
    for (int i = 0; i < DD; i++) acc += bq[i] * Wk[i * DD + n];
    bp[n] = acc;
}

// ---------------------------------------------------------------------------
// Generic tiled TF32 wmma GEMM: C[M,N] = A[M,K] * B[K,N] (+bias[n]) (+add[m,n])
// colA: A stored so A[m,k] = Aptr[k*lda + m]   (i.e. we want A = stored^T)
// colB: B stored so B[k,n] = Bptr[n*ldb + k]   (i.e. B = stored^T)
// Requires M%128==0, N%64==0, K%32==0 (true for all our shapes).
// ---------------------------------------------------------------------------
#define TILE_M 128
#define TILE_N 64
#define TILE_K 32
#define A_PAD 36
#define B_PAD 68

__global__ __launch_bounds__(256) void gemm_tf32_kernel(
    const float* __restrict__ A, const float* __restrict__ B,
    float* __restrict__ C,
    int M, int N, int K, int lda, int ldb, int ldc,
    int colA, int colB,
    const float* __restrict__ bias, const float* __restrict__ addmat)
{
    __shared__ union SM {
        struct { float As[TILE_M][A_PAD]; float Bs[TILE_K][B_PAD]; } ab;
        float Cs[TILE_M][B_PAD];
    } sm;

    const int tid  = threadIdx.x;
    const int warp = tid >> 5;
    const int wm   = warp >> 1;   // 0..3
    const int wn   = warp & 1;    // 0..1
    const int bm   = blockIdx.y * TILE_M;
    const int bn   = blockIdx.x * TILE_N;

    wmma::fragment<wmma::accumulator, 16, 16, 8, float> cf[2][2];
    #pragma unroll
    for (int i = 0; i < 2; i++)
        #pragma unroll
        for (int j = 0; j < 2; j++)
            wmma::fill_fragment(cf[i][j], 0.0f);

    for (int kt = 0; kt < K; kt += TILE_K) {
        // ---- load A tile: As[r][k] = A[bm+r, kt+k]
        if (!colA) {
            #pragma unroll
            for (int i = 0; i < 4; i++) {
                int idx = tid + i * 256;          // 1024 float4 total
                int r   = idx >> 3;
                int c4  = (idx & 7) * 4;
                float4 v = *(const float4*)&A[(size_t)(bm + r) * lda + kt + c4];
                *(float4*)&sm.ab.As[r][c4] = v;
            }
        } else {
            #pragma unroll
            for (int i = 0; i < 16; i++) {
                int idx = tid + i * 256;          // 4096 scalars
                int r   = idx & 127;              // coalesced over m
                int k   = idx >> 7;
                sm.ab.As[r][k] = A[(size_t)(kt + k) * lda + bm + r];
            }
        }
        // ---- load B tile: Bs[k][n] = B[kt+k, bn+n]
        if (!colB) {
            #pragma unroll
            for (int i = 0; i < 2; i++) {
                int idx = tid + i * 256;          // 512 float4
                int k   = idx >> 4;
                int c4  = (idx & 15) * 4;
                float4 v = *(const float4*)&B[(size_t)(kt + k) * ldb + bn + c4];
                *(float4*)&sm.ab.Bs[k][c4] = v;
            }
        } else {
            #pragma unroll
            for (int i = 0; i < 8; i++) {
                int idx = tid + i * 256;          // 2048 scalars
                int k   = idx & 31;               // coalesced over k
                int n   = idx >> 5;
                sm.ab.Bs[k][n] = B[(size_t)(bn + n) * ldb + kt + k];
            }
        }
        __syncthreads();

        #pragma unroll
        for (int ks = 0; ks < TILE_K; ks += 8) {
            wmma::fragment<wmma::matrix_a, 16, 16, 8, wmma::precision::tf32, wmma::row_major> af[2];
            wmma::fragment<wmma::matrix_b, 16, 16, 8, wmma::precision::tf32, wmma::row_major> bf[2];
            #pragma unroll
            for (int i = 0; i < 2; i++) {
                wmma::load_matrix_sync(af[i], &sm.ab.As[wm * 32 + i * 16][ks], A_PAD);
                #pragma unroll
                for (int t = 0; t < af[i].num_elements; t++)
                    af[i].x[t] = wmma::__float_to_tf32(af[i].x[t]);
                wmma::load_matrix_sync(bf[i], &sm.ab.Bs[ks][wn * 32 + i * 16], B_PAD);
                #pragma unroll
                for (int t = 0; t < bf[i].num_elements; t++)
                    bf[i].x[t] = wmma::__float_to_tf32(bf[i].x[t]);
            }
            #pragma unroll
            for (int i = 0; i < 2; i++)
                #pragma unroll
                for (int j = 0; j < 2; j++)
                    wmma::mma_sync(cf[i][j], af[i], bf[j], cf[i][j]);
        }
        __syncthreads();
    }

    // ---- epilogue: frags -> smem -> (bias/add) -> global
    #pragma unroll
    for (int i = 0; i < 2; i++)
        #pragma unroll
        for (int j = 0; j < 2; j++)
            wmma::store_matrix_sync(&sm.Cs[wm * 32 + i * 16][wn * 32 + j * 16],
                                    cf[i][j], B_PAD, wmma::mem_row_major);
    __syncthreads();

    #pragma unroll
    for (int i = 0; i < 8; i++) {
        int idx = tid + i * 256;                  // 2048 float4 (128x64)
        int r   = idx >> 4;
        int c4  = (idx & 15) * 4;
        float4 v = *(float4*)&sm.Cs[r][c4];
        if (bias) {
            v.x += bias[bn + c4 + 0];
            v.y += bias[bn + c4 + 1];
            v.z += bias[bn + c4 + 2];
            v.w += bias[bn + c4 + 3];
        }
        if (addmat) {
            float4 a = *(const float4*)&addmat[(size_t)(bm + r) * ldc + bn + c4];
            v.x += a.x; v.y += a.y; v.z += a.z; v.w += a.w;
        }
        *(float4*)&C[(size_t)(bm + r) * ldc + bn + c4] = v;
    }
}

// ---------------------------------------------------------------------------
// Fused attention: scores_n = U_row . key_n ; probs = softmax(scores/50);
// ctx = sum_n probs_n * value_n.  One block per (b,s) row, 256 threads.
// ---------------------------------------------------------------------------
__global__ __launch_bounds__(256) void attn_kernel(
    const float* __restrict__ U,
    const float* __restrict__ key,
    const float* __restrict__ value,
    float* __restrict__ probs_out,
    float* __restrict__ ctx)
{
    const int row = blockIdx.x;
    const int tid = threadIdx.x;
    const float* u  = U     + (size_t)row * DD;
    const float* kp = key   + (size_t)row * NN * DD;
    const float* vp = value + (size_t)row * NN * DD;

    const float u0 = u[tid], u1 = u[tid + 256], u2 = u[tid + 512];

    float p[NN];
    #pragma unroll
    for (int n = 0; n < NN; n++) {
        const float* kr = kp + n * DD;
        p[n] = u0 * kr[tid] + u1 * kr[tid + 256] + u2 * kr[tid + 512];
    }
    // warp reduce each of the 8 partial scores
    #pragma unroll
    for (int n = 0; n < NN; n++)
        #pragma unroll
        for (int off = 16; off > 0; off >>= 1)
            p[n] += __shfl_down_sync(0xffffffffu, p[n], off);

    __shared__ float red[8][NN];
    __shared__ float probs[NN];
    const int lane = tid & 31, w = tid >> 5;
    if (lane == 0) {
        #pragma unroll
        for (int n = 0; n < NN; n++) red[w][n] = p[n];
    }
    __syncthreads();

    if (tid == 0) {
        float s[NN];
        #pragma unroll
        for (int n = 0; n < NN; n++) {
            float acc = 0.f;
            #pragma unroll
            for (int ww = 0; ww < 8; ww++) acc += red[ww][n];
            s[n] = acc;
        }
        float m = s[0];
        #pragma unroll
        for (int n = 1; n < NN; n++) m = fmaxf(m, s[n]);
        float e[NN], sum = 0.f;
        #pragma unroll
        for (int n = 0; n < NN; n++) { e[n] = expf((s[n] - m) * (1.0f / 50.0f)); sum += e[n]; }
        float inv = 1.f / sum;
        #pragma unroll
        for (int n = 0; n < NN; n++) probs[n] = e[n] * inv;
    }
    __syncthreads();

    if (tid < NN) probs_out[(size_t)row * NN + tid] = probs[tid];

    float pr[NN];
    #pragma unroll
    for (int n = 0; n < NN; n++) pr[n] = probs[n];

    float* cx = ctx + (size_t)row * DD;
    #pragma unroll
    for (int j = 0; j < 3; j++) {
        int d = tid + j * 256;
        float acc = 0.f;
        #pragma unroll
        for (int n = 0; n < NN; n++) acc += pr[n] * vp[n * DD + d];
        cx[d] = acc;
    }
}

// ---------------------------------------------------------------------------
extern "C" void kernel_launch(void* const* d_in, const int* in_sizes, int n_in,
                              void* d_out, int out_size) {
    const float* query    = (const float*)d_in[0];   // [B,S,D]
    const float* key      = (const float*)d_in[1];   // [B,S,N,D]
    const float* value    = (const float*)d_in[2];   // [B,S,N,D]
    const float* residual = (const float*)d_in[3];   // [B,S,D]
    const float* Wq       = (const float*)d_in[4];   // [D,D]
    const float* bq       = (const float*)d_in[5];   // [D]
    const float* Wk       = (const float*)d_in[6];   // [D,D]
    // d_in[7] = bk: provably irrelevant (constant logit shift across n)
    const float* Wv       = (const float*)d_in[8];   // [D,D]

    float* out       = (float*)d_out;
    float* probs_out = out;                          // [B,S,N]
    float* ctx_out   = out + (size_t)ROWS * NN;      // [B,S,D]

    float *U, *ctx, *Wp, *bp;
    cudaGetSymbolAddress((void**)&U,   g_U);
    cudaGetSymbolAddress((void**)&ctx, g_ctx);
    cudaGetSymbolAddress((void**)&Wp,  g_Wp);
    cudaGetSymbolAddress((void**)&bp,  g_bp);

    // 1) b' = bq @ Wk
    prep_bp_kernel<<<6, 128>>>(bq, Wk, bp);

    // 2) W' = Wq^T @ Wk   (A = Wq accessed col-major)
    {
        dim3 grid(DD / TILE_N, DD / TILE_M);  // (12, 6)
        gemm_tf32_kernel<<<grid, 256>>>(Wq, Wk, Wp, DD, DD, DD, DD, DD, DD,
                                        /*colA=*/1, /*colB=*/0, nullptr, nullptr);
    }

    // 3) U = query @ W' + b'
    {
        dim3 grid(DD / TILE_N, ROWS / TILE_M);  // (12, 128)
        gemm_tf32_kernel<<<grid, 256>>>(query, Wp, U, ROWS, DD, DD, DD, DD, DD,
                                        0, 0, bp, nullptr);
    }

    // 4) attention: probs + ctx
    attn_kernel<<<ROWS, 256>>>(U, key, value, probs_out, ctx);

    // 5) out_ctx = ctx @ Wv^T + residual   (B = Wv accessed col-major)
    {
        dim3 grid(DD / TILE_N, ROWS / TILE_M);  // (12, 128)
        gemm_tf32_kernel<<<grid, 256>>>(ctx, Wv, ctx_out, ROWS, DD, DD, DD, DD, DD,
                                        0, /*colB=*/1, nullptr, residual);
    }
}

// round 3
// speedup vs baseline: 1.0808x; 1.0808x over previous
#include <cuda_runtime.h>
#include <mma.h>
#include <cstdint>

using namespace nvcuda;

// Problem constants
#define BB 8
#define SS 2048
#define NN 8
#define DD 768
#define ROWS (BB*SS)          // 16384

// Scratch (device globals: allocation-free per harness rules)
__device__ float g_U[ROWS*DD];     // query @ (Wq^T Wk) + bq@Wk
__device__ float g_ctx[ROWS*DD];   // attention context
__device__ float g_Wp[DD*DD];      // Wq^T @ Wk
__device__ float g_WvT[DD*DD];     // Wv^T (row-major)
__device__ float g_bp[DD];         // bq @ Wk

// ---------------------------------------------------------------------------
// prep: b'[n] = sum_i bq[i] * Wk[i, n]
// ---------------------------------------------------------------------------
__global__ void prep_bp_kernel(const float* __restrict__ bq,
                               const float* __restrict__ Wk,
                               float* __restrict__ bp) {
    int n = blockIdx.x * blockDim.x + threadIdx.x;
    if (n >= DD) return;
    float acc = 0.f;
    #pragma unroll 4
    for (int i = 0; i < DD; i++) acc += bq[i] * Wk[i * DD + n];
    bp[n] = acc;
}

// ---------------------------------------------------------------------------
// transpose 768x768: out[j][i] = in[i][j]
// ---------------------------------------------------------------------------
__global__ void transpose_kernel(const float* __restrict__ in,
                                 float* __restrict__ out) {
    __shared__ float t[32][33];
    int bx = blockIdx.x * 32, by = blockIdx.y * 32;
    int tx = threadIdx.x, ty = threadIdx.y;  // 32 x 8
    #pragma unroll
    for (int i = 0; i < 4; i++)
        t[ty + i * 8][tx] = in[(size_t)(by + ty + i * 8) * DD + bx + tx];
    __syncthreads();
    #pragma unroll
    for (int i = 0; i < 4; i++)
        out[(size_t)(bx + ty + i * 8) * DD + by + tx] = t[tx][ty + i * 8];
}

// ---------------------------------------------------------------------------
// Small generic tiled TF32 wmma GEMM (used only for W' = Wq^T @ Wk, 768^3).
// colA: A[m,k] = Aptr[k*lda + m]
// ---------------------------------------------------------------------------
#define TILE_M 128
#define TILE_N 64
#define TILE_K 32
#define A_PAD 36
#define B_PAD 68

__global__ __launch_bounds__(256) void gemm_tf32_kernel(
    const float* __restrict__ A, const float* __restrict__ B,
    float* __restrict__ C,
    int M, int N, int K, int lda, int ldb, int ldc, int colA)
{
    __shared__ union SM {
        struct { float As[TILE_M][A_PAD]; float Bs[TILE_K][B_PAD]; } ab;
        float Cs[TILE_M][B_PAD];
    } sm;

    const int tid  = threadIdx.x;
    const int warp = tid >> 5;
    const int wm   = warp >> 1;
    const int wn   = warp & 1;
    const int bm   = blockIdx.y * TILE_M;
    const int bn   = blockIdx.x * TILE_N;

    wmma::fragment<wmma::accumulator, 16, 16, 8, float> cf[2][2];
    #pragma unroll
    for (int i = 0; i < 2; i++)
        #pragma unroll
        for (int j = 0; j < 2; j++)
            wmma::fill_fragment(cf[i][j], 0.0f);

    for (int kt = 0; kt < K; kt += TILE_K) {
        if (!colA) {
            #pragma unroll
            for (int i = 0; i < 4; i++) {
                int idx = tid + i * 256;
                int r   = idx >> 3;
                int c4  = (idx & 7) * 4;
                float4 v = *(const float4*)&A[(size_t)(bm + r) * lda + kt + c4];
                *(float4*)&sm.ab.As[r][c4] = v;
            }
        } else {
            #pragma unroll
            for (int i = 0; i < 16; i++) {
                int idx = tid + i * 256;
                int r   = idx & 127;
                int k   = idx >> 7;
                sm.ab.As[r][k] = A[(size_t)(kt + k) * lda + bm + r];
            }
        }
        #pragma unroll
        for (int i = 0; i < 2; i++) {
            int idx = tid + i * 256;
            int k   = idx >> 4;
            int c4  = (idx & 15) * 4;
            float4 v = *(const float4*)&B[(size_t)(kt + k) * ldb + bn + c4];
            *(float4*)&sm.ab.Bs[k][c4] = v;
        }
        __syncthreads();

        #pragma unroll
        for (int ks = 0; ks < TILE_K; ks += 8) {
            wmma::fragment<wmma::matrix_a, 16, 16, 8, wmma::precision::tf32, wmma::row_major> af[2];
            wmma::fragment<wmma::matrix_b, 16, 16, 8, wmma::precision::tf32, wmma::row_major> bf[2];
            #pragma unroll
            for (int i = 0; i < 2; i++) {
                wmma::load_matrix_sync(af[i], &sm.ab.As[wm * 32 + i * 16][ks], A_PAD);
                #pragma unroll
                for (int t = 0; t < af[i].num_elements; t++)
                    af[i].x[t] = wmma::__float_to_tf32(af[i].x[t]);
                wmma::load_matrix_sync(bf[i], &sm.ab.Bs[ks][wn * 32 + i * 16], B_PAD);
                #pragma unroll
                for (int t = 0; t < bf[i].num_elements; t++)
                    bf[i].x[t] = wmma::__float_to_tf32(bf[i].x[t]);
            }
            #pragma unroll
            for (int i = 0; i < 2; i++)
                #pragma unroll
                for (int j = 0; j < 2; j++)
                    wmma::mma_sync(cf[i][j], af[i], bf[j], cf[i][j]);
        }
        __syncthreads();
    }

    #pragma unroll
    for (int i = 0; i < 2; i++)
        #pragma unroll
        for (int j = 0; j < 2; j++)
            wmma::store_matrix_sync(&sm.Cs[wm * 32 + i * 16][wn * 32 + j * 16],
                                    cf[i][j], B_PAD, wmma::mem_row_major);
    __syncthreads();

    #pragma unroll
    for (int i = 0; i < 8; i++) {
        int idx = tid + i * 256;
        int r   = idx >> 4;
        int c4  = (idx & 15) * 4;
        float4 v = *(float4*)&sm.Cs[r][c4];
        *(float4*)&C[(size_t)(bm + r) * ldc + bn + c4] = v;
    }
}

// ---------------------------------------------------------------------------
// Fast pipelined TF32 GEMM: C[M,768] = A[M,768] * B[768,768] (+bias)(+addmat)
// Pure row-major. 128x128x16 tiles, 3-stage cp.async pipeline.
// ---------------------------------------------------------------------------
#define FM 128
#define FN 128
#define FK 16
#define FSTAGES 3
#define FKT (DD / FK)          // 48
#define APADF 20               // FK + 4
#define BPADF 132              // FN + 4
#define A_STG (FM * APADF)     // 2560 floats
#define B_STG (FK * BPADF)     // 2112 floats
#define DYN_SMEM ((FSTAGES * (A_STG + B_STG)) * 4)   // 56064 bytes

__device__ __forceinline__ void cp_async16(float* smem, const float* gmem) {
    uint32_t s = (uint32_t)__cvta_generic_to_shared(smem);
    asm volatile("cp.async.cg.shared.global [%0], [%1], 16;\n" :: "r"(s), "l"(gmem));
}

__device__ __forceinline__ void load_tile_f(float* As, float* Bs,
                                            const float* __restrict__ A,
                                            const float* __restrict__ B,
                                            int bm, int bn, int kt, int tid) {
    #pragma unroll
    for (int t = 0; t < 2; t++) {
        int idx = tid + t * 256;           // 512 chunks: 128 rows x 4 chunks
        int r   = idx >> 2;
        int c4  = (idx & 3) * 4;
        cp_async16(&As[r * APADF + c4], &A[(size_t)(bm + r) * DD + kt + c4]);
    }
    #pragma unroll
    for (int t = 0; t < 2; t++) {
        int idx = tid + t * 256;           // 512 chunks: 16 rows x 32 chunks
        int k   = idx >> 5;
        int c4  = (idx & 31) * 4;
        cp_async16(&Bs[k * BPADF + c4], &B[(size_t)(kt + k) * DD + bn + c4]);
    }
}

extern __shared__ float dynsm[];

__global__ __launch_bounds__(256, 2) void gemm_fast_kernel(
    const float* __restrict__ A, const float* __restrict__ B,
    float* __restrict__ C, int M,
    const float* __restrict__ bias, const float* __restrict__ addmat)
{
    float* As = dynsm;
    float* Bs = dynsm + FSTAGES * A_STG;

    const int tid  = threadIdx.x;
    const int warp = tid >> 5;
    const int lane = tid & 31;
    const int wm   = warp & 3;    // 0..3 -> rows wm*32
    const int wn   = warp >> 2;   // 0..1 -> cols wn*64
    const int bm   = blockIdx.y * FM;
    const int bn   = blockIdx.x * FN;

    wmma::fragment<wmma::accumulator, 16, 16, 8, float> cf[2][4];
    #pragma unroll
    for (int i = 0; i < 2; i++)
        #pragma unroll
        for (int j = 0; j < 4; j++)
            wmma::fill_fragment(cf[i][j], 0.0f);

    // prologue: prefetch first FSTAGES-1 tiles
    #pragma unroll
    for (int s = 0; s < FSTAGES - 1; s++) {
        load_tile_f(&As[s * A_STG], &Bs[s * B_STG], A, B, bm, bn, s * FK, tid);
        asm volatile("cp.async.commit_group;\n");
    }

    for (int it = 0; it < FKT; it++) {
        asm volatile("cp.async.wait_group %0;\n" :: "n"(FSTAGES - 2));
        __syncthreads();

        int nk = it + FSTAGES - 1;
        if (nk < FKT) {
            int buf = nk % FSTAGES;
            load_tile_f(&As[buf * A_STG], &Bs[buf * B_STG], A, B, bm, bn, nk * FK, tid);
        }
        asm volatile("cp.async.commit_group;\n");

        const float* as = &As[(it % FSTAGES) * A_STG];
        const float* bs = &Bs[(it % FSTAGES) * B_STG];

        #pragma unroll
        for (int ks = 0; ks < FK; ks += 8) {
            wmma::fragment<wmma::matrix_a, 16, 16, 8, wmma::precision::tf32, wmma::row_major> af[2];
            wmma::fragment<wmma::matrix_b, 16, 16, 8, wmma::precision::tf32, wmma::row_major> bf[4];
            #pragma unroll
            for (int i = 0; i < 2; i++) {
                wmma::load_matrix_sync(af[i], &as[(wm * 32 + i * 16) * APADF + ks], APADF);
                #pragma unroll
                for (int t = 0; t < af[i].num_elements; t++)
                    af[i].x[t] = wmma::__float_to_tf32(af[i].x[t]);
            }
            #pragma unroll
            for (int j = 0; j < 4; j++) {
                wmma::load_matrix_sync(bf[j], &bs[ks * BPADF + wn * 64 + j * 16], BPADF);
                #pragma unroll
                for (int t = 0; t < bf[j].num_elements; t++)
                    bf[j].x[t] = wmma::__float_to_tf32(bf[j].x[t]);
            }
            #pragma unroll
            for (int i = 0; i < 2; i++)
                #pragma unroll
                for (int j = 0; j < 4; j++)
                    wmma::mma_sync(cf[i][j], af[i], bf[j], cf[i][j]);
        }
        __syncthreads();
    }

    // epilogue: per-warp 16x16 staging through smem (reuses pipeline smem)
    float* stg = dynsm + warp * (16 * APADF);
    #pragma unroll
    for (int i = 0; i < 2; i++) {
        #pragma unroll
        for (int j = 0; j < 4; j++) {
            wmma::store_matrix_sync(stg, cf[i][j], APADF, wmma::mem_row_major);
            __syncwarp();
            int r     = lane >> 1;           // 0..15
            int cbase = (lane & 1) * 8;      // 0 or 8
            int grow  = bm + wm * 32 + i * 16 + r;
            int gcol  = bn + wn * 64 + j * 16 + cbase;
            float4 v0 = *(float4*)&stg[r * APADF + cbase];
            float4 v1 = *(float4*)&stg[r * APADF + cbase + 4];
            if (bias) {
                float4 b0 = *(const float4*)&bias[gcol];
                float4 b1 = *(const float4*)&bias[gcol + 4];
                v0.x += b0.x; v0.y += b0.y; v0.z += b0.z; v0.w += b0.w;
                v1.x += b1.x; v1.y += b1.y; v1.z += b1.z; v1.w += b1.w;
            }
            if (addmat) {
                float4 a0 = *(const float4*)&addmat[(size_t)grow * DD + gcol];
                float4 a1 = *(const float4*)&addmat[(size_t)grow * DD + gcol + 4];
                v0.x += a0.x; v0.y += a0.y; v0.z += a0.z; v0.w += a0.w;
                v1.x += a1.x; v1.y += a1.y; v1.z += a1.z; v1.w += a1.w;
            }
            *(float4*)&C[(size_t)grow * DD + gcol]     = v0;
            *(float4*)&C[(size_t)grow * DD + gcol + 4] = v1;
            __syncwarp();
        }
    }
}

// ---------------------------------------------------------------------------
// Fused attention: scores_n = U_row . key_n ; probs = softmax(scores/50);
// ctx = sum_n probs_n * value_n.  One block per (b,s) row, 256 threads.
// ---------------------------------------------------------------------------
__global__ __launch_bounds__(256) void attn_kernel(
    const float* __restrict__ U,
    const float* __restrict__ key,
    const float* __restrict__ value,
    float* __restrict__ probs_out,
    float* __restrict__ ctx)
{
    const int row = blockIdx.x;
    const int tid = threadIdx.x;
    const float* u  = U     + (size_t)row * DD;
    const float* kp = key   + (size_t)row * NN * DD;
    const float* vp = value + (size_t)row * NN * DD;

    const float u0 = u[tid], u1 = u[tid + 256], u2 = u[tid + 512];

    float p[NN];
    #pragma unroll
    for (int n = 0; n < NN; n++) {
        const float* kr = kp + n * DD;
        p[n] = u0 * kr[tid] + u1 * kr[tid + 256] + u2 * kr[tid + 512];
    }
    #pragma unroll
    for (int n = 0; n < NN; n++)
        #pragma unroll
        for (int off = 16; off > 0; off >>= 1)
            p[n] += __shfl_down_sync(0xffffffffu, p[n], off);

    __shared__ float red[8][NN];
    __shared__ float probs[NN];
    const int lane = tid & 31, w = tid >> 5;
    if (lane == 0) {
        #pragma unroll
        for (int n = 0; n < NN; n++) red[w][n] = p[n];
    }
    __syncthreads();

    if (tid == 0) {
        float s[NN];
        #pragma unroll
        for (int n = 0; n < NN; n++) {
            float acc = 0.f;
            #pragma unroll
            for (int ww = 0; ww < 8; ww++) acc += red[ww][n];
            s[n] = acc;
        }
        float m = s[0];
        #pragma unroll
        for (int n = 1; n < NN; n++) m = fmaxf(m, s[n]);
        float e[NN], sum = 0.f;
        #pragma unroll
        for (int n = 0; n < NN; n++) { e[n] = expf((s[n] - m) * (1.0f / 50.0f)); sum += e[n]; }
        float inv = 1.f / sum;
        #pragma unroll
        for (int n = 0; n < NN; n++) probs[n] = e[n] * inv;
    }
    __syncthreads();

    if (tid < NN) probs_out[(size_t)row * NN + tid] = probs[tid];

    float pr[NN];
    #pragma unroll
    for (int n = 0; n < NN; n++) pr[n] = probs[n];

    float* cx = ctx + (size_t)row * DD;
    #pragma unroll
    for (int j = 0; j < 3; j++) {
        int d = tid + j * 256;
        float acc = 0.f;
        #pragma unroll
        for (int n = 0; n < NN; n++) acc += pr[n] * vp[n * DD + d];
        cx[d] = acc;
    }
}

// ---------------------------------------------------------------------------
extern "C" void kernel_launch(void* const* d_in, const int* in_sizes, int n_in,
                              void* d_out, int out_size) {
    const float* query    = (const float*)d_in[0];   // [B,S,D]
    const float* key      = (const float*)d_in[1];   // [B,S,N,D]
    const float* value    = (const float*)d_in[2];   // [B,S,N,D]
    const float* residual = (const float*)d_in[3];   // [B,S,D]
    const float* Wq       = (const float*)d_in[4];   // [D,D]
    const float* bq       = (const float*)d_in[5];   // [D]
    const float* Wk       = (const float*)d_in[6];   // [D,D]
    // d_in[7] = bk: constant logit shift across n -> dropped by softmax
    const float* Wv       = (const float*)d_in[8];   // [D,D]

    float* out       = (float*)d_out;
    float* probs_out = out;                          // [B,S,N]
    float* ctx_out   = out + (size_t)ROWS * NN;      // [B,S,D]

    float *U, *ctx, *Wp, *WvT, *bp;
    cudaGetSymbolAddress((void**)&U,   g_U);
    cudaGetSymbolAddress((void**)&ctx, g_ctx);
    cudaGetSymbolAddress((void**)&Wp,  g_Wp);
    cudaGetSymbolAddress((void**)&WvT, g_WvT);
    cudaGetSymbolAddress((void**)&bp,  g_bp);

    static bool attr_set = false;
    if (!attr_set) {
        cudaFuncSetAttribute(gemm_fast_kernel,
                             cudaFuncAttributeMaxDynamicSharedMemorySize, DYN_SMEM);
        attr_set = true;
    }

    // 1) b' = bq @ Wk
    prep_bp_kernel<<<6, 128>>>(bq, Wk, bp);

    // 2) W' = Wq^T @ Wk
    {
        dim3 grid(DD / TILE_N, DD / TILE_M);  // (12, 6)
        gemm_tf32_kernel<<<grid, 256>>>(Wq, Wk, Wp, DD, DD, DD, DD, DD, DD, 1);
    }

    // 3) WvT = Wv^T
    {
        dim3 grid(DD / 32, DD / 32);
        transpose_kernel<<<grid, dim3(32, 8)>>>(Wv, WvT);
    }

    // 4) U = query @ W' + b'
    {
        dim3 grid(DD / FN, ROWS / FM);  // (6, 128)
        gemm_fast_kernel<<<grid, 256, DYN_SMEM>>>(query, Wp, U, ROWS, bp, nullptr);
    }

    // 5) attention: probs + ctx
    attn_kernel<<<ROWS, 256>>>(U, key, value, probs_out, ctx);

    // 6) out_ctx = ctx @ WvT + residual
    {
        dim3 grid(DD / FN, ROWS / FM);  // (6, 128)
        gemm_fast_kernel<<<grid, 256, DYN_SMEM>>>(ctx, WvT, ctx_out, ROWS, nullptr, residual);
    }
}

// round 6
// speedup vs baseline: 2.0064x; 1.8564x over previous
#include <cuda_runtime.h>
#include <cuda.h>
#include <cuda_bf16.h>
#include <mma.h>
#include <cstdint>

using namespace nvcuda;

#define BB 8
#define SS 2048
#define NN 8
#define DD 768
#define ROWS (BB*SS)          // 16384

__device__ __align__(256) float         g_U[ROWS*DD];
__device__ __align__(256) float         g_ctx[ROWS*DD];
__device__ __align__(256) __nv_bfloat16 g_qb[ROWS*DD];
__device__ __align__(256) __nv_bfloat16 g_Wppb[DD*DD];   // [n,k] = sum_i Wk[i,n]*Wq[i,k]
__device__ __align__(256) float         g_bp[DD];

// ======================= portable PTX helpers (<= sm_90) ====================
__device__ __forceinline__ uint32_t smem_u32(const void* p) {
    uint32_t a;
    asm("{ .reg .u64 t; cvta.to.shared.u64 t, %1; cvt.u32.u64 %0, t; }"
        : "=r"(a) : "l"(p));
    return a;
}

#define MBAR_INIT(addr, cnt) \
    asm volatile("mbarrier.init.shared.b64 [%0], %1;" :: "r"((uint32_t)(addr)), "r"((uint32_t)(cnt)) : "memory")
#define MBAR_EXPECT_TX(addr, bytes) \
    asm volatile("mbarrier.arrive.expect_tx.shared.b64 _, [%0], %1;" \
                 :: "r"((uint32_t)(addr)), "r"((uint32_t)(bytes)) : "memory")
#define MBAR_ARRIVE(addr) \
    asm volatile("mbarrier.arrive.shared.b64 _, [%0];" :: "r"((uint32_t)(addr)) : "memory")

#define MBAR_WAIT(mbar_addr, phase_parity) do {                                   \
    uint32_t _mbar = (uint32_t)(mbar_addr);                                        \
    uint32_t _par  = (uint32_t)(phase_parity);                                     \
    uint32_t _done;                                                                \
    asm volatile(                                                                  \
        "{\n\t.reg .pred p;\n\t"                                                   \
        "mbarrier.try_wait.parity.acquire.cta.shared::cta.b64 p, [%1], %2;\n\t"    \
        "selp.b32 %0, 1, 0, p;\n\t}"                                               \
        : "=r"(_done) : "r"(_mbar), "r"(_par) : "memory");                         \
    if (!_done) {                                                                  \
        asm volatile(                                                              \
            "{\n\t.reg .pred P1;\n\t"                                              \
            "WAIT_LOOP_%=:\n\t"                                                    \
            "mbarrier.try_wait.parity.acquire.cta.shared::cta.b64 P1, [%0], %1, 0x989680;\n\t" \
            "@P1 bra.uni WAIT_DONE_%=;\n\t"                                        \
            "bra.uni WAIT_LOOP_%=;\n\t"                                            \
            "WAIT_DONE_%=:\n\t}"                                                   \
            :: "r"(_mbar), "r"(_par) : "memory");                                  \
    }                                                                              \
} while (0)

#define TMA_2D(dst, map, x, y, mbar) \
    asm volatile("cp.async.bulk.tensor.2d.shared::cluster.global.tile.mbarrier::complete_tx::bytes " \
        "[%0], [%1, {%2, %3}], [%4];" \
        :: "r"((uint32_t)(dst)), "l"(map), "r"((int)(x)), "r"((int)(y)), \
           "r"((uint32_t)(mbar)) : "memory")

#define LDSM_X4(r0, r1, r2, r3, addr) \
    asm volatile("ldmatrix.sync.aligned.m8n8.x4.shared.b16 {%0,%1,%2,%3}, [%4];" \
        : "=r"(r0), "=r"(r1), "=r"(r2), "=r"(r3) : "r"((uint32_t)(addr)))

#define MMA_BF16(d, a, b) \
    asm volatile("mma.sync.aligned.m16n8k16.row.col.f32.bf16.bf16.f32 " \
        "{%0,%1,%2,%3}, {%4,%5,%6,%7}, {%8,%9}, {%0,%1,%2,%3};" \
        : "+f"((d)[0]), "+f"((d)[1]), "+f"((d)[2]), "+f"((d)[3]) \
        : "r"((a)[0]), "r"((a)[1]), "r"((a)[2]), "r"((a)[3]), \
          "r"((b)[0]), "r"((b)[1]))

#define MMA_TF32(d, a, b) \
    asm volatile("mma.sync.aligned.m16n8k8.row.col.f32.tf32.tf32.f32 " \
        "{%0,%1,%2,%3}, {%4,%5,%6,%7}, {%8,%9}, {%0,%1,%2,%3};" \
        : "+f"((d)[0]), "+f"((d)[1]), "+f"((d)[2]), "+f"((d)[3]) \
        : "r"((a)[0]), "r"((a)[1]), "r"((a)[2]), "r"((a)[3]), \
          "r"((b)[0]), "r"((b)[1]))

#define F2TF32(u, f) asm("cvt.rna.tf32.f32 %0, %1;" : "=r"(u) : "f"(f))

// Pipeline layout (both GEMMs): 4 stages x (16KB A + 16KB B)
#define ST 4
#define STB 32768
#define GSMEM (1024 + ST * STB)   // 132096 bytes

// ===========================================================================
// GEMM1 (bf16): U[16384,768] = qb @ Wppb^T + bias. Tile 128x128, K-chunk 64.
// ===========================================================================
__global__ __launch_bounds__(256, 1) void gemm1_bf16_tma(
    const __grid_constant__ CUtensorMap mA,
    const __grid_constant__ CUtensorMap mB,
    float* __restrict__ C, const float* __restrict__ bias)
{
    extern __shared__ __align__(1024) char smem[];
    const uint32_t sb = smem_u32(smem);
    const int tid = threadIdx.x, lane = tid & 31, wid = tid >> 5;
    const int wm = wid & 3, wn = wid >> 2;
    const int bm = blockIdx.y * 128, bn = blockIdx.x * 128;
    const uint32_t fullb = sb, emptyb = sb + 32;
    const uint32_t tiles = sb + 1024;
    const int NCH = 12;   // 768 / 64

    if (tid == 0) {
        #pragma unroll
        for (int s = 0; s < ST; s++) { MBAR_INIT(fullb + 8*s, 1); MBAR_INIT(emptyb + 8*s, 8); }
        asm volatile("fence.proxy.async.shared::cta;" ::: "memory");
    }
    __syncthreads();

    if (tid == 0) {
        #pragma unroll
        for (int s = 0; s < ST - 1; s++) {
            MBAR_EXPECT_TX(fullb + 8*s, STB);
            uint32_t dA = tiles + s * STB;
            TMA_2D(dA,         &mA, s * 64, bm, fullb + 8*s);
            TMA_2D(dA + 16384, &mB, s * 64, bn, fullb + 8*s);
        }
    }

    float d[2][8][4];
    #pragma unroll
    for (int i = 0; i < 2; i++)
        #pragma unroll
        for (int j = 0; j < 8; j++)
            #pragma unroll
            for (int k = 0; k < 4; k++) d[i][j][k] = 0.f;

    for (int it = 0; it < NCH; it++) {
        if (tid == 0) {
            int pre = it + ST - 1;
            if (pre < NCH) {
                int s = pre & 3;
                if (pre >= ST) MBAR_WAIT(emptyb + 8*s, ((pre >> 2) - 1) & 1);
                MBAR_EXPECT_TX(fullb + 8*s, STB);
                uint32_t dA = tiles + s * STB;
                TMA_2D(dA,         &mA, pre * 64, bm, fullb + 8*s);
                TMA_2D(dA + 16384, &mB, pre * 64, bn, fullb + 8*s);
            }
        }
        int s = it & 3;
        MBAR_WAIT(fullb + 8*s, (it >> 2) & 1);
        uint32_t sA = tiles + s * STB;
        uint32_t sB = sA + 16384;

        #pragma unroll
        for (int ks = 0; ks < 4; ks++) {
            uint32_t col = (uint32_t)(ks * 32 + ((lane >> 4) << 4));
            uint32_t a[2][4];
            #pragma unroll
            for (int i = 0; i < 2; i++) {
                int m = wm * 32 + i * 16 + (lane & 15);
                uint32_t addr = sA + (uint32_t)m * 128 + (col ^ (uint32_t)((m & 7) * 16));
                LDSM_X4(a[i][0], a[i][1], a[i][2], a[i][3], addr);
            }
            uint32_t b[8][2];
            #pragma unroll
            for (int jj = 0; jj < 4; jj++) {
                int n = wn * 64 + jj * 16 + (lane & 15);
                uint32_t addr = sB + (uint32_t)n * 128 + (col ^ (uint32_t)((n & 7) * 16));
                uint32_t r0, r1, r2, r3;
                LDSM_X4(r0, r1, r2, r3, addr);
                b[2*jj][0] = r0;   b[2*jj][1] = r2;
                b[2*jj+1][0] = r1; b[2*jj+1][1] = r3;
            }
            #pragma unroll
            for (int i = 0; i < 2; i++)
                #pragma unroll
                for (int j = 0; j < 8; j++)
                    MMA_BF16(d[i][j], a[i], b[j]);
        }
        __syncwarp();
        if (lane == 0) MBAR_ARRIVE(emptyb + 8*s);
    }

    #pragma unroll
    for (int i = 0; i < 2; i++) {
        int r0 = bm + wm * 32 + i * 16 + (lane >> 2);
        #pragma unroll
        for (int j = 0; j < 8; j++) {
            int gc = bn + wn * 64 + j * 8 + (lane & 3) * 2;
            float2 bv = *(const float2*)&bias[gc];
            *(float2*)&C[(size_t)r0 * DD + gc] =
                make_float2(d[i][j][0] + bv.x, d[i][j][1] + bv.y);
            *(float2*)&C[(size_t)(r0 + 8) * DD + gc] =
                make_float2(d[i][j][2] + bv.x, d[i][j][3] + bv.y);
        }
    }
}

// ===========================================================================
// GEMM2 (tf32): out = ctx @ Wv^T + residual. Tile 128x128, K-chunk 32.
// ===========================================================================
__global__ __launch_bounds__(256, 1) void gemm2_tf32_tma(
    const __grid_constant__ CUtensorMap mA,
    const __grid_constant__ CUtensorMap mB,
    float* __restrict__ C, const float* __restrict__ addmat)
{
    extern __shared__ __align__(1024) char smem[];
    const uint32_t sb = smem_u32(smem);
    const int tid = threadIdx.x, lane = tid & 31, wid = tid >> 5;
    const int wm = wid & 3, wn = wid >> 2;
    const int bm = blockIdx.y * 128, bn = blockIdx.x * 128;
    const uint32_t fullb = sb, emptyb = sb + 32;
    const uint32_t tiles = sb + 1024;
    const int NCH = 24;   // 768 / 32

    if (tid == 0) {
        #pragma unroll
        for (int s = 0; s < ST; s++) { MBAR_INIT(fullb + 8*s, 1); MBAR_INIT(emptyb + 8*s, 8); }
        asm volatile("fence.proxy.async.shared::cta;" ::: "memory");
    }
    __syncthreads();

    if (tid == 0) {
        #pragma unroll
        for (int s = 0; s < ST - 1; s++) {
            MBAR_EXPECT_TX(fullb + 8*s, STB);
            uint32_t dA = tiles + s * STB;
            TMA_2D(dA,         &mA, s * 32, bm, fullb + 8*s);
            TMA_2D(dA + 16384, &mB, s * 32, bn, fullb + 8*s);
        }
    }

    float d[2][8][4];
    #pragma unroll
    for (int i = 0; i < 2; i++)
        #pragma unroll
        for (int j = 0; j < 8; j++)
            #pragma unroll
            for (int k = 0; k < 4; k++) d[i][j][k] = 0.f;

    for (int it = 0; it < NCH; it++) {
        if (tid == 0) {
            int pre = it + ST - 1;
            if (pre < NCH) {
                int s = pre & 3;
                if (pre >= ST) MBAR_WAIT(emptyb + 8*s, ((pre >> 2) - 1) & 1);
                MBAR_EXPECT_TX(fullb + 8*s, STB);
                uint32_t dA = tiles + s * STB;
                TMA_2D(dA,         &mA, pre * 32, bm, fullb + 8*s);
                TMA_2D(dA + 16384, &mB, pre * 32, bn, fullb + 8*s);
            }
        }
        int s = it & 3;
        MBAR_WAIT(fullb + 8*s, (it >> 2) & 1);
        const char* As = smem + 1024 + s * STB;
        const char* Bs = As + 16384;

        #pragma unroll
        for (int ks = 0; ks < 4; ks++) {
            uint32_t cb = (uint32_t)((ks * 8 + (lane & 3)) * 4);
            uint32_t a[2][4];
            #pragma unroll
            for (int i = 0; i < 2; i++) {
                int r = wm * 32 + i * 16 + (lane >> 2);
                uint32_t x0 = cb ^ (uint32_t)((r & 7) * 16);
                uint32_t x1 = (cb + 16) ^ (uint32_t)((r & 7) * 16);
                float f0 = *(const float*)(As + (size_t)r * 128 + x0);
                float f1 = *(const float*)(As + (size_t)(r + 8) * 128 + x0);
                float f2 = *(const float*)(As + (size_t)r * 128 + x1);
                float f3 = *(const float*)(As + (size_t)(r + 8) * 128 + x1);
                F2TF32(a[i][0], f0); F2TF32(a[i][1], f1);
                F2TF32(a[i][2], f2); F2TF32(a[i][3], f3);
            }
            #pragma unroll
            for (int j = 0; j < 8; j++) {
                int n = wn * 64 + j * 8 + (lane >> 2);
                uint32_t x0 = cb ^ (uint32_t)((n & 7) * 16);
                uint32_t x1 = (cb + 16) ^ (uint32_t)((n & 7) * 16);
                float f0 = *(const float*)(Bs + (size_t)n * 128 + x0);
                float f1 = *(const float*)(Bs + (size_t)n * 128 + x1);
                uint32_t b[2];
                F2TF32(b[0], f0); F2TF32(b[1], f1);
                #pragma unroll
                for (int i = 0; i < 2; i++)
                    MMA_TF32(d[i][j], a[i], b);
            }
        }
        __syncwarp();
        if (lane == 0) MBAR_ARRIVE(emptyb + 8*s);
    }

    #pragma unroll
    for (int i = 0; i < 2; i++) {
        int r0 = bm + wm * 32 + i * 16 + (lane >> 2);
        #pragma unroll
        for (int j = 0; j < 8; j++) {
            int gc = bn + wn * 64 + j * 8 + (lane & 3) * 2;
            float2 a0 = *(const float2*)&addmat[(size_t)r0 * DD + gc];
            float2 a1 = *(const float2*)&addmat[(size_t)(r0 + 8) * DD + gc];
            *(float2*)&C[(size_t)r0 * DD + gc] =
                make_float2(d[i][j][0] + a0.x, d[i][j][1] + a0.y);
            *(float2*)&C[(size_t)(r0 + 8) * DD + gc] =
                make_float2(d[i][j][2] + a1.x, d[i][j][3] + a1.y);
        }
    }
}

// ---------------------------------------------------------------------------
__global__ void prep_bp_kernel(const float* __restrict__ bq,
                               const float* __restrict__ Wk,
                               float* __restrict__ bp) {
    int n = blockIdx.x * blockDim.x + threadIdx.x;
    if (n >= DD) return;
    float acc = 0.f;
    #pragma unroll 4
    for (int i = 0; i < DD; i++) acc += bq[i] * Wk[i * DD + n];
    bp[n] = acc;
}

__global__ void convq_kernel(const float4* __restrict__ in,
                             uint2* __restrict__ out, int n4) {
    int i = blockIdx.x * blockDim.x + threadIdx.x;
    if (i >= n4) return;
    float4 v = in[i];
    __nv_bfloat162 p0 = __floats2bfloat162_rn(v.x, v.y);
    __nv_bfloat162 p1 = __floats2bfloat162_rn(v.z, v.w);
    out[i] = make_uint2(*(uint32_t*)&p0, *(uint32_t*)&p1);
}

// ---------------------------------------------------------------------------
// W''[n,k] = sum_i Wk[i,n] * Wq[i,k]  (wmma tf32, 768^3, bf16 out)
// ---------------------------------------------------------------------------
#define TILE_M 128
#define TILE_N 64
#define TILE_K 32
#define A_PAD 36
#define B_PAD 68

__global__ __launch_bounds__(256) void gemm_wpp_kernel(
    const float* __restrict__ A, const float* __restrict__ B,
    __nv_bfloat16* __restrict__ Cb)
{
    __shared__ union SM {
        struct { float As[TILE_M][A_PAD]; float Bs[TILE_K][B_PAD]; } ab;
        float Cs[TILE_M][B_PAD];
    } sm;

    const int tid  = threadIdx.x;
    const int warp = tid >> 5;
    const int wm   = warp >> 1;
    const int wn   = warp & 1;
    const int bm   = blockIdx.y * TILE_M;
    const int bn   = blockIdx.x * TILE_N;

    wmma::fragment<wmma::accumulator, 16, 16, 8, float> cf[2][2];
    #pragma unroll
    for (int i = 0; i < 2; i++)
        #pragma unroll
        for (int j = 0; j < 2; j++)
            wmma::fill_fragment(cf[i][j], 0.0f);

    for (int kt = 0; kt < DD; kt += TILE_K) {
        #pragma unroll
        for (int i = 0; i < 16; i++) {
            int idx = tid + i * 256;
            int r   = idx & 127;
            int k   = idx >> 7;
            sm.ab.As[r][k] = A[(size_t)(kt + k) * DD + bm + r];
        }
        #pragma unroll
        for (int i = 0; i < 2; i++) {
            int idx = tid + i * 256;
            int k   = idx >> 4;
            int c4  = (idx & 15) * 4;
            float4 v = *(const float4*)&B[(size_t)(kt + k) * DD + bn + c4];
            *(float4*)&sm.ab.Bs[k][c4] = v;
        }
        __syncthreads();

        #pragma unroll
        for (int ks = 0; ks < TILE_K; ks += 8) {
            wmma::fragment<wmma::matrix_a, 16, 16, 8, wmma::precision::tf32, wmma::row_major> af[2];
            wmma::fragment<wmma::matrix_b, 16, 16, 8, wmma::precision::tf32, wmma::row_major> bf[2];
            #pragma unroll
            for (int i = 0; i < 2; i++) {
                wmma::load_matrix_sync(af[i], &sm.ab.As[wm * 32 + i * 16][ks], A_PAD);
                #pragma unroll
                for (int t = 0; t < af[i].num_elements; t++)
                    af[i].x[t] = wmma::__float_to_tf32(af[i].x[t]);
                wmma::load_matrix_sync(bf[i], &sm.ab.Bs[ks][wn * 32 + i * 16], B_PAD);
                #pragma unroll
                for (int t = 0; t < bf[i].num_elements; t++)
                    bf[i].x[t] = wmma::__float_to_tf32(bf[i].x[t]);
            }
            #pragma unroll
            for (int i = 0; i < 2; i++)
                #pragma unroll
                for (int j = 0; j < 2; j++)
                    wmma::mma_sync(cf[i][j], af[i], bf[j], cf[i][j]);
        }
        __syncthreads();
    }

    #pragma unroll
    for (int i = 0; i < 2; i++)
        #pragma unroll
        for (int j = 0; j < 2; j++)
            wmma::store_matrix_sync(&sm.Cs[wm * 32 + i * 16][wn * 32 + j * 16],
                                    cf[i][j], B_PAD, wmma::mem_row_major);
    __syncthreads();

    #pragma unroll
    for (int i = 0; i < 8; i++) {
        int idx = tid + i * 256;
        int r   = idx >> 4;
        int c4  = (idx & 15) * 4;
        float4 v = *(float4*)&sm.Cs[r][c4];
        __nv_bfloat162 p0 = __floats2bfloat162_rn(v.x, v.y);
        __nv_bfloat162 p1 = __floats2bfloat162_rn(v.z, v.w);
        *(uint2*)&Cb[(size_t)(bm + r) * DD + bn + c4] =
            make_uint2(*(uint32_t*)&p0, *(uint32_t*)&p1);
    }
}

// ---------------------------------------------------------------------------
__global__ __launch_bounds__(256) void attn_kernel(
    const float* __restrict__ U,
    const float* __restrict__ key,
    const float* __restrict__ value,
    float* __restrict__ probs_out,
    float* __restrict__ ctx)
{
    const int row = blockIdx.x;
    const int tid = threadIdx.x;
    const float* u  = U     + (size_t)row * DD;
    const float* kp = key   + (size_t)row * NN * DD;
    const float* vp = value + (size_t)row * NN * DD;

    const float u0 = u[tid], u1 = u[tid + 256], u2 = u[tid + 512];

    float p[NN];
    #pragma unroll
    for (int n = 0; n < NN; n++) {
        const float* kr = kp + n * DD;
        p[n] = u0 * kr[tid] + u1 * kr[tid + 256] + u2 * kr[tid + 512];
    }
    #pragma unroll
    for (int n = 0; n < NN; n++)
        #pragma unroll
        for (int off = 16; off > 0; off >>= 1)
            p[n] += __shfl_down_sync(0xffffffffu, p[n], off);

    __shared__ float red[8][NN];
    __shared__ float probs[NN];
    const int lane = tid & 31, w = tid >> 5;
    if (lane == 0) {
        #pragma unroll
        for (int n = 0; n < NN; n++) red[w][n] = p[n];
    }
    __syncthreads();

    if (tid == 0) {
        float s[NN];
        #pragma unroll
        for (int n = 0; n < NN; n++) {
            float acc = 0.f;
            #pragma unroll
            for (int ww = 0; ww < 8; ww++) acc += red[ww][n];
            s[n] = acc;
        }
        float m = s[0];
        #pragma unroll
        for (int n = 1; n < NN; n++) m = fmaxf(m, s[n]);
        float e[NN], sum = 0.f;
        #pragma unroll
        for (int n = 0; n < NN; n++) { e[n] = expf((s[n] - m) * (1.0f / 50.0f)); sum += e[n]; }
        float inv = 1.f / sum;
        #pragma unroll
        for (int n = 0; n < NN; n++) probs[n] = e[n] * inv;
    }
    __syncthreads();

    if (tid < NN) probs_out[(size_t)row * NN + tid] = probs[tid];

    float pr[NN];
    #pragma unroll
    for (int n = 0; n < NN; n++) pr[n] = probs[n];

    float* cx = ctx + (size_t)row * DD;
    #pragma unroll
    for (int j = 0; j < 3; j++) {
        int d = tid + j * 256;
        float acc = 0.f;
        #pragma unroll
        for (int n = 0; n < NN; n++) acc += pr[n] * vp[n * DD + d];
        cx[d] = acc;
    }
}

// ---------------------------------------------------------------------------
typedef CUresult (*EncodeFn)(CUtensorMap*, CUtensorMapDataType, cuuint32_t, void*,
                             const cuuint64_t*, const cuuint64_t*, const cuuint32_t*,
                             const cuuint32_t*, CUtensorMapInterleave, CUtensorMapSwizzle,
                             CUtensorMapL2promotion, CUtensorMapFloatOOBfill);

static void make_map2d(EncodeFn enc, CUtensorMap* m, void* ptr,
                       CUtensorMapDataType dt, int elsz,
                       uint64_t d0, uint64_t d1, uint32_t b0, uint32_t b1) {
    cuuint64_t dims[2]    = {d0, d1};
    cuuint64_t strides[1] = {d0 * (uint64_t)elsz};
    cuuint32_t box[2]     = {b0, b1};
    cuuint32_t es[2]      = {1, 1};
    enc(m, dt, 2, ptr, dims, strides, box, es,
        CU_TENSOR_MAP_INTERLEAVE_NONE, CU_TENSOR_MAP_SWIZZLE_128B,
        CU_TENSOR_MAP_L2_PROMOTION_L2_128B, CU_TENSOR_MAP_FLOAT_OOB_FILL_NONE);
}

extern "C" void kernel_launch(void* const* d_in, const int* in_sizes, int n_in,
                              void* d_out, int out_size) {
    const float* query    = (const float*)d_in[0];
    const float* key      = (const float*)d_in[1];
    const float* value    = (const float*)d_in[2];
    const float* residual = (const float*)d_in[3];
    const float* Wq       = (const float*)d_in[4];
    const float* bq       = (const float*)d_in[5];
    const float* Wk       = (const float*)d_in[6];
    // d_in[7] = bk: constant logit shift across n -> dropped by softmax
    const float* Wv       = (const float*)d_in[8];

    float* out       = (float*)d_out;
    float* probs_out = out;
    float* ctx_out   = out + (size_t)ROWS * NN;

    float *U, *ctx, *bp;
    __nv_bfloat16 *qb, *Wppb;
    cudaGetSymbolAddress((void**)&U,    g_U);
    cudaGetSymbolAddress((void**)&ctx,  g_ctx);
    cudaGetSymbolAddress((void**)&qb,   g_qb);
    cudaGetSymbolAddress((void**)&Wppb, g_Wppb);
    cudaGetSymbolAddress((void**)&bp,   g_bp);

    cudaFuncSetAttribute(gemm1_bf16_tma,
                         cudaFuncAttributeMaxDynamicSharedMemorySize, GSMEM);
    cudaFuncSetAttribute(gemm2_tf32_tma,
                         cudaFuncAttributeMaxDynamicSharedMemorySize, GSMEM);

    EncodeFn enc = nullptr;
    cudaDriverEntryPointQueryResult qr;
    cudaGetDriverEntryPointByVersion("cuTensorMapEncodeTiled", (void**)&enc,
                                     12000, cudaEnableDefault, &qr);

    CUtensorMap mQ, mWpp, mCtx, mWv;
    make_map2d(enc, &mQ,   qb,          CU_TENSOR_MAP_DATA_TYPE_BFLOAT16, 2, DD, ROWS, 64, 128);
    make_map2d(enc, &mWpp, Wppb,        CU_TENSOR_MAP_DATA_TYPE_BFLOAT16, 2, DD, DD,   64, 128);
    make_map2d(enc, &mCtx, ctx,         CU_TENSOR_MAP_DATA_TYPE_FLOAT32,  4, DD, ROWS, 32, 128);
    make_map2d(enc, &mWv,  (void*)Wv,   CU_TENSOR_MAP_DATA_TYPE_FLOAT32,  4, DD, DD,   32, 128);

    // 1) b' = bq @ Wk
    prep_bp_kernel<<<6, 128>>>(bq, Wk, bp);

    // 2) W''[n,k] = sum_i Wk[i,n] * Wq[i,k]  (bf16 out)
    {
        dim3 grid(DD / TILE_N, DD / TILE_M);
        gemm_wpp_kernel<<<grid, 256>>>(Wk, Wq, Wppb);
    }

    // 3) query -> bf16
    convq_kernel<<<(ROWS * DD / 4 + 255) / 256, 256>>>(
        (const float4*)query, (uint2*)qb, ROWS * DD / 4);

    // 4) U = qb @ W''^T + b'
    {
        dim3 grid(DD / 128, ROWS / 128);   // (6, 128)
        gemm1_bf16_tma<<<grid, 256, GSMEM>>>(mQ, mWpp, U, bp);
    }

    // 5) attention
    attn_kernel<<<ROWS, 256>>>(U, key, value, probs_out, ctx);

    // 6) out = ctx @ Wv^T + residual
    {
        dim3 grid(DD / 128, ROWS / 128);   // (6, 128)
        gemm2_tf32_tma<<<grid, 256, GSMEM>>>(mCtx, mWv, ctx_out, residual);
    }
}

// round 7
// speedup vs baseline: 2.3374x; 1.1650x over previous
#include <cuda_runtime.h>
#include <cuda.h>
#include <cuda_bf16.h>
#include <cstdint>

#define BB 8
#define SS 2048
#define NN 8
#define DD 768
#define ROWS (BB*SS)          // 16384

__device__ __align__(256) float         g_U[ROWS*DD];
__device__ __align__(256) float         g_ctx[ROWS*DD];    // tf32-rounded
__device__ __align__(256) __nv_bfloat16 g_qb[ROWS*DD];
__device__ __align__(256) __nv_bfloat16 g_Wppb[DD*DD];     // [n,k]
__device__ __align__(256) float         g_Wpp[DD*DD];      // fp32 staging
__device__ __align__(256) __nv_bfloat16 g_WkTb[DD*DD];     // Wk^T bf16
__device__ __align__(256) __nv_bfloat16 g_WqTb[DD*DD];     // Wq^T bf16
__device__ __align__(256) float         g_Wv32[DD*DD];     // Wv tf32-rounded
__device__ __align__(256) float         g_bp[DD];

// ======================= portable PTX helpers (<= sm_90) ====================
__device__ __forceinline__ uint32_t smem_u32(const void* p) {
    uint32_t a;
    asm("{ .reg .u64 t; cvta.to.shared.u64 t, %1; cvt.u32.u64 %0, t; }"
        : "=r"(a) : "l"(p));
    return a;
}

#define MBAR_INIT(addr, cnt) \
    asm volatile("mbarrier.init.shared.b64 [%0], %1;" :: "r"((uint32_t)(addr)), "r"((uint32_t)(cnt)) : "memory")
#define MBAR_EXPECT_TX(addr, bytes) \
    asm volatile("mbarrier.arrive.expect_tx.shared.b64 _, [%0], %1;" \
                 :: "r"((uint32_t)(addr)), "r"((uint32_t)(bytes)) : "memory")
#define MBAR_ARRIVE(addr) \
    asm volatile("mbarrier.arrive.shared.b64 _, [%0];" :: "r"((uint32_t)(addr)) : "memory")

#define MBAR_WAIT(mbar_addr, phase_parity) do {                                   \
    uint32_t _mbar = (uint32_t)(mbar_addr);                                        \
    uint32_t _par  = (uint32_t)(phase_parity);                                     \
    uint32_t _done;                                                                \
    asm volatile(                                                                  \
        "{\n\t.reg .pred p;\n\t"                                                   \
        "mbarrier.try_wait.parity.acquire.cta.shared::cta.b64 p, [%1], %2;\n\t"    \
        "selp.b32 %0, 1, 0, p;\n\t}"                                               \
        : "=r"(_done) : "r"(_mbar), "r"(_par) : "memory");                         \
    if (!_done) {                                                                  \
        asm volatile(                                                              \
            "{\n\t.reg .pred P1;\n\t"                                              \
            "WAIT_LOOP_%=:\n\t"                                                    \
            "mbarrier.try_wait.parity.acquire.cta.shared::cta.b64 P1, [%0], %1, 0x989680;\n\t" \
            "@P1 bra.uni WAIT_DONE_%=;\n\t"                                        \
            "bra.uni WAIT_LOOP_%=;\n\t"                                            \
            "WAIT_DONE_%=:\n\t}"                                                   \
            :: "r"(_mbar), "r"(_par) : "memory");                                  \
    }                                                                              \
} while (0)

#define TMA_2D(dst, map, x, y, mbar) \
    asm volatile("cp.async.bulk.tensor.2d.shared::cluster.global.tile.mbarrier::complete_tx::bytes " \
        "[%0], [%1, {%2, %3}], [%4];" \
        :: "r"((uint32_t)(dst)), "l"(map), "r"((int)(x)), "r"((int)(y)), \
           "r"((uint32_t)(mbar)) : "memory")

#define LDSM_X4(r0, r1, r2, r3, addr) \
    asm volatile("ldmatrix.sync.aligned.m8n8.x4.shared.b16 {%0,%1,%2,%3}, [%4];" \
        : "=r"(r0), "=r"(r1), "=r"(r2), "=r"(r3) : "r"((uint32_t)(addr)))

#define MMA_BF16(d, a, b) \
    asm volatile("mma.sync.aligned.m16n8k16.row.col.f32.bf16.bf16.f32 " \
        "{%0,%1,%2,%3}, {%4,%5,%6,%7}, {%8,%9}, {%0,%1,%2,%3};" \
        : "+f"((d)[0]), "+f"((d)[1]), "+f"((d)[2]), "+f"((d)[3]) \
        : "r"((a)[0]), "r"((a)[1]), "r"((a)[2]), "r"((a)[3]), \
          "r"((b)[0]), "r"((b)[1]))

#define MMA_TF32(d, a, b) \
    asm volatile("mma.sync.aligned.m16n8k8.row.col.f32.tf32.tf32.f32 " \
        "{%0,%1,%2,%3}, {%4,%5,%6,%7}, {%8,%9}, {%0,%1,%2,%3};" \
        : "+f"((d)[0]), "+f"((d)[1]), "+f"((d)[2]), "+f"((d)[3]) \
        : "r"((a)[0]), "r"((a)[1]), "r"((a)[2]), "r"((a)[3]), \
          "r"((b)[0]), "r"((b)[1]))

__device__ __forceinline__ float tf32r(float f) {
    uint32_t u;
    asm("cvt.rna.tf32.f32 %0, %1;" : "=r"(u) : "f"(f));
    return __uint_as_float(u);
}

// Pipeline: 3 stages x (16KB A + 16KB B) -> 99,328B -> 2 CTAs/SM
#define ST 3
#define STB 32768
#define GSMEM (1024 + ST * STB)

// ===========================================================================
// GEMM1 (bf16): C[M,768] = A @ B^T (+bias). Tile 128x128, K-chunk 64 (NCH=12).
// ===========================================================================
__global__ __launch_bounds__(256, 2) void gemm1_bf16_tma(
    const __grid_constant__ CUtensorMap mA,
    const __grid_constant__ CUtensorMap mB,
    float* __restrict__ C, const float* __restrict__ bias)
{
    extern __shared__ __align__(1024) char smem[];
    const uint32_t sb = smem_u32(smem);
    const int tid = threadIdx.x, lane = tid & 31, wid = tid >> 5;
    const int wm = wid & 3, wn = wid >> 2;
    const int bm = blockIdx.y * 128, bn = blockIdx.x * 128;
    const uint32_t fullb = sb, emptyb = sb + 32;
    const uint32_t tiles = sb + 1024;
    const int NCH = 12;

    if (tid == 0) {
        #pragma unroll
        for (int s = 0; s < ST; s++) { MBAR_INIT(fullb + 8*s, 1); MBAR_INIT(emptyb + 8*s, 8); }
        asm volatile("fence.proxy.async.shared::cta;" ::: "memory");
    }
    __syncthreads();

    if (tid == 0) {
        #pragma unroll
        for (int s = 0; s < ST - 1; s++) {
            MBAR_EXPECT_TX(fullb + 8*s, STB);
            uint32_t dA = tiles + s * STB;
            TMA_2D(dA,         &mA, s * 64, bm, fullb + 8*s);
            TMA_2D(dA + 16384, &mB, s * 64, bn, fullb + 8*s);
        }
    }

    float d[2][8][4];
    #pragma unroll
    for (int i = 0; i < 2; i++)
        #pragma unroll
        for (int j = 0; j < 8; j++)
            #pragma unroll
            for (int k = 0; k < 4; k++) d[i][j][k] = 0.f;

    for (int it = 0; it < NCH; it++) {
        if (tid == 0) {
            int pre = it + ST - 1;
            if (pre < NCH) {
                int s = pre % ST;
                if (pre >= ST) MBAR_WAIT(emptyb + 8*s, ((pre / ST) - 1) & 1);
                MBAR_EXPECT_TX(fullb + 8*s, STB);
                uint32_t dA = tiles + s * STB;
                TMA_2D(dA,         &mA, pre * 64, bm, fullb + 8*s);
                TMA_2D(dA + 16384, &mB, pre * 64, bn, fullb + 8*s);
            }
        }
        int s = it % ST;
        MBAR_WAIT(fullb + 8*s, (it / ST) & 1);
        uint32_t sA = tiles + s * STB;
        uint32_t sB = sA + 16384;

        #pragma unroll
        for (int ks = 0; ks < 4; ks++) {
            uint32_t col = (uint32_t)(ks * 32 + ((lane >> 4) << 4));
            uint32_t a[2][4];
            #pragma unroll
            for (int i = 0; i < 2; i++) {
                int m = wm * 32 + i * 16 + (lane & 15);
                uint32_t addr = sA + (uint32_t)m * 128 + (col ^ (uint32_t)((m & 7) * 16));
                LDSM_X4(a[i][0], a[i][1], a[i][2], a[i][3], addr);
            }
            uint32_t b[8][2];
            #pragma unroll
            for (int jj = 0; jj < 4; jj++) {
                int n = wn * 64 + jj * 16 + (lane & 15);
                uint32_t addr = sB + (uint32_t)n * 128 + (col ^ (uint32_t)((n & 7) * 16));
                uint32_t r0, r1, r2, r3;
                LDSM_X4(r0, r1, r2, r3, addr);
                b[2*jj][0] = r0;   b[2*jj][1] = r2;
                b[2*jj+1][0] = r1; b[2*jj+1][1] = r3;
            }
            #pragma unroll
            for (int i = 0; i < 2; i++)
                #pragma unroll
                for (int j = 0; j < 8; j++)
                    MMA_BF16(d[i][j], a[i], b[j]);
        }
        __syncwarp();
        if (lane == 0) MBAR_ARRIVE(emptyb + 8*s);
    }

    #pragma unroll
    for (int i = 0; i < 2; i++) {
        int r0 = bm + wm * 32 + i * 16 + (lane >> 2);
        #pragma unroll
        for (int j = 0; j < 8; j++) {
            int gc = bn + wn * 64 + j * 8 + (lane & 3) * 2;
            float2 bv = bias ? *(const float2*)&bias[gc] : make_float2(0.f, 0.f);
            *(float2*)&C[(size_t)r0 * DD + gc] =
                make_float2(d[i][j][0] + bv.x, d[i][j][1] + bv.y);
            *(float2*)&C[(size_t)(r0 + 8) * DD + gc] =
                make_float2(d[i][j][2] + bv.x, d[i][j][3] + bv.y);
        }
    }
}

// ===========================================================================
// GEMM2 (tf32, ldmatrix): out = ctx @ Wv^T + residual. Tile 128x128, K-chunk 32.
// A, B are pre-rounded to tf32 in global memory.
// ===========================================================================
__global__ __launch_bounds__(256, 2) void gemm2_tf32_tma(
    const __grid_constant__ CUtensorMap mA,
    const __grid_constant__ CUtensorMap mB,
    float* __restrict__ C, const float* __restrict__ addmat)
{
    extern __shared__ __align__(1024) char smem[];
    const uint32_t sb = smem_u32(smem);
    const int tid = threadIdx.x, lane = tid & 31, wid = tid >> 5;
    const int wm = wid & 3, wn = wid >> 2;
    const int bm = blockIdx.y * 128, bn = blockIdx.x * 128;
    const uint32_t fullb = sb, emptyb = sb + 32;
    const uint32_t tiles = sb + 1024;
    const int NCH = 24;
    const int lt = lane >> 3;   // ldmatrix tile index 0..3
    const int lr = lane & 7;    // row within tile

    if (tid == 0) {
        #pragma unroll
        for (int s = 0; s < ST; s++) { MBAR_INIT(fullb + 8*s, 1); MBAR_INIT(emptyb + 8*s, 8); }
        asm volatile("fence.proxy.async.shared::cta;" ::: "memory");
    }
    __syncthreads();

    if (tid == 0) {
        #pragma unroll
        for (int s = 0; s < ST - 1; s++) {
            MBAR_EXPECT_TX(fullb + 8*s, STB);
            uint32_t dA = tiles + s * STB;
            TMA_2D(dA,         &mA, s * 32, bm, fullb + 8*s);
            TMA_2D(dA + 16384, &mB, s * 32, bn, fullb + 8*s);
        }
    }

    float d[2][8][4];
    #pragma unroll
    for (int i = 0; i < 2; i++)
        #pragma unroll
        for (int j = 0; j < 8; j++)
            #pragma unroll
            for (int k = 0; k < 4; k++) d[i][j][k] = 0.f;

    for (int it = 0; it < NCH; it++) {
        if (tid == 0) {
            int pre = it + ST - 1;
            if (pre < NCH) {
                int s = pre % ST;
                if (pre >= ST) MBAR_WAIT(emptyb + 8*s, ((pre / ST) - 1) & 1);
                MBAR_EXPECT_TX(fullb + 8*s, STB);
                uint32_t dA = tiles + s * STB;
                TMA_2D(dA,         &mA, pre * 32, bm, fullb + 8*s);
                TMA_2D(dA + 16384, &mB, pre * 32, bn, fullb + 8*s);
            }
        }
        int s = it % ST;
        MBAR_WAIT(fullb + 8*s, (it / ST) & 1);
        uint32_t sA = tiles + s * STB;
        uint32_t sB = sA + 16384;

        // Fragments via ldmatrix: an 8x8 b16 tile == 8x4 fp32 tile whose
        // per-thread layout (t/4, t%4) matches the tf32 mma fragment exactly.
        #pragma unroll
        for (int ks = 0; ks < 4; ks++) {
            uint32_t a[2][4];
            #pragma unroll
            for (int i = 0; i < 2; i++) {
                int m = wm * 32 + i * 16 + (lt & 1) * 8 + lr;
                uint32_t col = (uint32_t)(ks * 32 + (lt >> 1) * 16);
                uint32_t addr = sA + (uint32_t)m * 128 + (col ^ (uint32_t)((m & 7) * 16));
                LDSM_X4(a[i][0], a[i][1], a[i][2], a[i][3], addr);
            }
            uint32_t b[8][2];
            #pragma unroll
            for (int jj = 0; jj < 4; jj++) {
                int n = wn * 64 + jj * 16 + (lt >> 1) * 8 + lr;
                uint32_t col = (uint32_t)(ks * 32 + (lt & 1) * 16);
                uint32_t addr = sB + (uint32_t)n * 128 + (col ^ (uint32_t)((n & 7) * 16));
                uint32_t r0, r1, r2, r3;
                LDSM_X4(r0, r1, r2, r3, addr);
                b[2*jj][0] = r0;   b[2*jj][1] = r1;
                b[2*jj+1][0] = r2; b[2*jj+1][1] = r3;
            }
            #pragma unroll
            for (int i = 0; i < 2; i++)
                #pragma unroll
                for (int j = 0; j < 8; j++)
                    MMA_TF32(d[i][j], a[i], b[j]);
        }
        __syncwarp();
        if (lane == 0) MBAR_ARRIVE(emptyb + 8*s);
    }

    #pragma unroll
    for (int i = 0; i < 2; i++) {
        int r0 = bm + wm * 32 + i * 16 + (lane >> 2);
        #pragma unroll
        for (int j = 0; j < 8; j++) {
            int gc = bn + wn * 64 + j * 8 + (lane & 3) * 2;
            float2 a0 = *(const float2*)&addmat[(size_t)r0 * DD + gc];
            float2 a1 = *(const float2*)&addmat[(size_t)(r0 + 8) * DD + gc];
            *(float2*)&C[(size_t)r0 * DD + gc] =
                make_float2(d[i][j][0] + a0.x, d[i][j][1] + a0.y);
            *(float2*)&C[(size_t)(r0 + 8) * DD + gc] =
                make_float2(d[i][j][2] + a1.x, d[i][j][3] + a1.y);
        }
    }
}

// ---------------------------------------------------------------------------
__global__ void prep_bp_kernel(const float* __restrict__ bq,
                               const float* __restrict__ Wk,
                               float* __restrict__ bp) {
    int n = blockIdx.x * blockDim.x + threadIdx.x;
    if (n >= DD) return;
    float acc = 0.f;
    #pragma unroll 4
    for (int i = 0; i < DD; i++) acc += bq[i] * Wk[i * DD + n];
    bp[n] = acc;
}

// fp32 -> bf16 elementwise (float4-wide)
__global__ void convb_kernel(const float4* __restrict__ in,
                             uint2* __restrict__ out, int n4) {
    int i = blockIdx.x * blockDim.x + threadIdx.x;
    if (i >= n4) return;
    float4 v = in[i];
    __nv_bfloat162 p0 = __floats2bfloat162_rn(v.x, v.y);
    __nv_bfloat162 p1 = __floats2bfloat162_rn(v.z, v.w);
    out[i] = make_uint2(*(uint32_t*)&p0, *(uint32_t*)&p1);
}

// fp32 -> tf32-rounded fp32 elementwise
__global__ void convt_kernel(const float4* __restrict__ in,
                             float4* __restrict__ out, int n4) {
    int i = blockIdx.x * blockDim.x + threadIdx.x;
    if (i >= n4) return;
    float4 v = in[i];
    out[i] = make_float4(tf32r(v.x), tf32r(v.y), tf32r(v.z), tf32r(v.w));
}

// transpose 768x768 + fp32 -> bf16
__global__ void tconv_kernel(const float* __restrict__ in,
                             __nv_bfloat16* __restrict__ out) {
    __shared__ float t[32][33];
    int bx = blockIdx.x * 32, by = blockIdx.y * 32;
    int tx = threadIdx.x, ty = threadIdx.y;   // 32 x 8
    #pragma unroll
    for (int i = 0; i < 4; i++)
        t[ty + i * 8][tx] = in[(size_t)(by + ty + i * 8) * DD + bx + tx];
    __syncthreads();
    #pragma unroll
    for (int i = 0; i < 4; i++)
        out[(size_t)(bx + ty + i * 8) * DD + by + tx] =
            __float2bfloat16(t[tx][ty + i * 8]);
}

// ---------------------------------------------------------------------------
// Attention: 192 threads, float4 lanes. ctx written tf32-rounded.
// ---------------------------------------------------------------------------
__global__ __launch_bounds__(192) void attn_kernel(
    const float* __restrict__ U,
    const float* __restrict__ key,
    const float* __restrict__ value,
    float* __restrict__ probs_out,
    float* __restrict__ ctx)
{
    const int row = blockIdx.x;
    const int tid = threadIdx.x;               // 0..191
    const float4* u4 = (const float4*)(U + (size_t)row * DD);
    const float4* k4 = (const float4*)(key + (size_t)row * NN * DD);
    const float4* v4 = (const float4*)(value + (size_t)row * NN * DD);

    const float4 u = u4[tid];

    float p[NN];
    #pragma unroll
    for (int n = 0; n < NN; n++) {
        float4 k = k4[n * 192 + tid];
        p[n] = u.x * k.x + u.y * k.y + u.z * k.z + u.w * k.w;
    }
    #pragma unroll
    for (int n = 0; n < NN; n++)
        #pragma unroll
        for (int off = 16; off > 0; off >>= 1)
            p[n] += __shfl_down_sync(0xffffffffu, p[n], off);

    __shared__ float red[6][NN];
    __shared__ float probs[NN];
    const int lane = tid & 31, w = tid >> 5;
    if (lane == 0) {
        #pragma unroll
        for (int n = 0; n < NN; n++) red[w][n] = p[n];
    }
    __syncthreads();

    if (tid == 0) {
        float s[NN];
        #pragma unroll
        for (int n = 0; n < NN; n++) {
            float acc = 0.f;
            #pragma unroll
            for (int ww = 0; ww < 6; ww++) acc += red[ww][n];
            s[n] = acc;
        }
        float m = s[0];
        #pragma unroll
        for (int n = 1; n < NN; n++) m = fmaxf(m, s[n]);
        float e[NN], sum = 0.f;
        #pragma unroll
        for (int n = 0; n < NN; n++) { e[n] = expf((s[n] - m) * (1.0f / 50.0f)); sum += e[n]; }
        float inv = 1.f / sum;
        #pragma unroll
        for (int n = 0; n < NN; n++) probs[n] = e[n] * inv;
    }
    __syncthreads();

    if (tid < NN) probs_out[(size_t)row * NN + tid] = probs[tid];

    float pr[NN];
    #pragma unroll
    for (int n = 0; n < NN; n++) pr[n] = probs[n];

    float4 acc = make_float4(0.f, 0.f, 0.f, 0.f);
    #pragma unroll
    for (int n = 0; n < NN; n++) {
        float4 v = v4[n * 192 + tid];
        acc.x += pr[n] * v.x; acc.y += pr[n] * v.y;
        acc.z += pr[n] * v.z; acc.w += pr[n] * v.w;
    }
    ((float4*)(ctx + (size_t)row * DD))[tid] =
        make_float4(tf32r(acc.x), tf32r(acc.y), tf32r(acc.z), tf32r(acc.w));
}

// ---------------------------------------------------------------------------
typedef CUresult (*EncodeFn)(CUtensorMap*, CUtensorMapDataType, cuuint32_t, void*,
                             const cuuint64_t*, const cuuint64_t*, const cuuint32_t*,
                             const cuuint32_t*, CUtensorMapInterleave, CUtensorMapSwizzle,
                             CUtensorMapL2promotion, CUtensorMapFloatOOBfill);

static void make_map2d(EncodeFn enc, CUtensorMap* m, void* ptr,
                       CUtensorMapDataType dt, int elsz,
                       uint64_t d0, uint64_t d1, uint32_t b0, uint32_t b1) {
    cuuint64_t dims[2]    = {d0, d1};
    cuuint64_t strides[1] = {d0 * (uint64_t)elsz};
    cuuint32_t box[2]     = {b0, b1};
    cuuint32_t es[2]      = {1, 1};
    enc(m, dt, 2, ptr, dims, strides, box, es,
        CU_TENSOR_MAP_INTERLEAVE_NONE, CU_TENSOR_MAP_SWIZZLE_128B,
        CU_TENSOR_MAP_L2_PROMOTION_L2_128B, CU_TENSOR_MAP_FLOAT_OOB_FILL_NONE);
}

extern "C" void kernel_launch(void* const* d_in, const int* in_sizes, int n_in,
                              void* d_out, int out_size) {
    const float* query    = (const float*)d_in[0];
    const float* key      = (const float*)d_in[1];
    const float* value    = (const float*)d_in[2];
    const float* residual = (const float*)d_in[3];
    const float* Wq       = (const float*)d_in[4];
    const float* bq       = (const float*)d_in[5];
    const float* Wk       = (const float*)d_in[6];
    // d_in[7] = bk: constant logit shift across heads -> dropped by softmax
    const float* Wv       = (const float*)d_in[8];

    float* out       = (float*)d_out;
    float* probs_out = out;
    float* ctx_out   = out + (size_t)ROWS * NN;

    float *U, *ctx, *Wpp, *Wv32, *bp;
    __nv_bfloat16 *qb, *Wppb, *WkTb, *WqTb;
    cudaGetSymbolAddress((void**)&U,    g_U);
    cudaGetSymbolAddress((void**)&ctx,  g_ctx);
    cudaGetSymbolAddress((void**)&qb,   g_qb);
    cudaGetSymbolAddress((void**)&Wppb, g_Wppb);
    cudaGetSymbolAddress((void**)&Wpp,  g_Wpp);
    cudaGetSymbolAddress((void**)&WkTb, g_WkTb);
    cudaGetSymbolAddress((void**)&WqTb, g_WqTb);
    cudaGetSymbolAddress((void**)&Wv32, g_Wv32);
    cudaGetSymbolAddress((void**)&bp,   g_bp);

    cudaFuncSetAttribute(gemm1_bf16_tma,
                         cudaFuncAttributeMaxDynamicSharedMemorySize, GSMEM);
    cudaFuncSetAttribute(gemm2_tf32_tma,
                         cudaFuncAttributeMaxDynamicSharedMemorySize, GSMEM);

    EncodeFn enc = nullptr;
    cudaDriverEntryPointQueryResult qr;
    cudaGetDriverEntryPointByVersion("cuTensorMapEncodeTiled", (void**)&enc,
                                     12000, cudaEnableDefault, &qr);

    CUtensorMap mQ, mWpp, mCtx, mWv, mWkT, mWqT;
    make_map2d(enc, &mQ,   qb,   CU_TENSOR_MAP_DATA_TYPE_BFLOAT16, 2, DD, ROWS, 64, 128);
    make_map2d(enc, &mWpp, Wppb, CU_TENSOR_MAP_DATA_TYPE_BFLOAT16, 2, DD, DD,   64, 128);
    make_map2d(enc, &mWkT, WkTb, CU_TENSOR_MAP_DATA_TYPE_BFLOAT16, 2, DD, DD,   64, 128);
    make_map2d(enc, &mWqT, WqTb, CU_TENSOR_MAP_DATA_TYPE_BFLOAT16, 2, DD, DD,   64, 128);
    make_map2d(enc, &mCtx, ctx,  CU_TENSOR_MAP_DATA_TYPE_FLOAT32,  4, DD, ROWS, 32, 128);
    make_map2d(enc, &mWv,  Wv32, CU_TENSOR_MAP_DATA_TYPE_FLOAT32,  4, DD, DD,   32, 128);

    dim3 tgrid(DD / 32, DD / 32);

    // 1) b' = bq @ Wk
    prep_bp_kernel<<<6, 128>>>(bq, Wk, bp);

    // 2) transposed bf16 copies of Wk, Wq; Wv tf32-rounded; query bf16
    tconv_kernel<<<tgrid, dim3(32, 8)>>>(Wk, WkTb);
    tconv_kernel<<<tgrid, dim3(32, 8)>>>(Wq, WqTb);
    convt_kernel<<<(DD * DD / 4 + 255) / 256, 256>>>(
        (const float4*)Wv, (float4*)Wv32, DD * DD / 4);
    convb_kernel<<<(ROWS * DD / 4 + 255) / 256, 256>>>(
        (const float4*)query, (uint2*)qb, ROWS * DD / 4);

    // 3) W''[n,k] = sum_i Wk[i,n] * Wq[i,k]  via fast bf16 kernel, then -> bf16
    gemm1_bf16_tma<<<dim3(DD / 128, DD / 128), 256, GSMEM>>>(mWkT, mWqT, Wpp, nullptr);
    convb_kernel<<<(DD * DD / 4 + 255) / 256, 256>>>(
        (const float4*)Wpp, (uint2*)Wppb, DD * DD / 4);

    // 4) U = qb @ W''^T + b'
    gemm1_bf16_tma<<<dim3(DD / 128, ROWS / 128), 256, GSMEM>>>(mQ, mWpp, U, bp);

    // 5) attention (ctx written tf32-rounded)
    attn_kernel<<<ROWS, 192>>>(U, key, value, probs_out, ctx);

    // 6) out = ctx @ Wv^T + residual
    gemm2_tf32_tma<<<dim3(DD / 128, ROWS / 128), 256, GSMEM>>>(mCtx, mWv, ctx_out, residual);
}